// round 15
// baseline (speedup 1.0000x reference)
#include <cuda_runtime.h>
#include <math.h>
#include <float.h>

#define BB 8
#define NN 4096
#define KK 9
#define NPTS (BB*NN)        /* 32768 */
#define ROWS (NPTS*KK)      /* 294912 */
#define QB 32               /* queries per block (knn) */
#define QW 4                /* queries per warp */
#define CAP 32              /* survivor capacity per query */
#define NBF 256             /* feat partial blocks */
#define NSPL 3              /* mlp edge splits */
#define NBM (NBF*NSPL)      /* 768 mlp partial blocks */

typedef unsigned long long ull;

// Scratch (allocation-free: __device__ globals)
__device__ int   g_nbr[NPTS*KK];
__device__ float g_rel[27*NPTS];     // SoA: [(e*3+c)*NPTS + gid]
__device__ float g_p1[NBF*20];
__device__ float g_p2[NBM*20];
__device__ float g_s1v[20];          // mu[10], inv[10]
__device__ float g_s2v[20];
__device__ float g_hmax3[NSPL*NPTS*10];
__device__ float g_hmin3[NSPL*NPTS*10];

__device__ __forceinline__ bool dless(float d1, int j1, float d2, int j2) {
    return d1 < d2 || (d1 == d2 && j1 < j2);
}

// ---- packed f32x2 helpers: two bit-identical fp32 ops per issue -----------
__device__ __forceinline__ ull pack2(float lo, float hi) {
    ull r; asm("mov.b64 %0, {%1, %2};" : "=l"(r) : "f"(lo), "f"(hi)); return r;
}
__device__ __forceinline__ void unpack2(ull v, float& lo, float& hi) {
    asm("mov.b64 {%0, %1}, %2;" : "=f"(lo), "=f"(hi) : "l"(v));
}
__device__ __forceinline__ ull fma2(ull a, ull b, ull c) {
    ull d; asm("fma.rn.f32x2 %0, %1, %2, %3;" : "=l"(d) : "l"(a), "l"(b), "l"(c));
    return d;
}
__device__ __forceinline__ ull mul2(ull a, ull b) {
    ull d; asm("mul.rn.f32x2 %0, %1, %2;" : "=l"(d) : "l"(a), "l"(b)); return d;
}

// Warp-distributed sorted top-10 insert (validated R4-R14 fallback).
__device__ __forceinline__ void warp_insert(float nd, int nj, float& sd, int& si,
                                            const int lane) {
    const float pd = __shfl_up_sync(0xffffffffu, sd, 1);
    const int   pi = __shfl_up_sync(0xffffffffu, si, 1);
    const bool pcur  = dless(nd, nj, sd, si);
    const bool pprev = (lane > 0) && dless(nd, nj, pd, pi);
    if (pcur) { sd = pprev ? pd : nd; si = pprev ? pi : nj; }
}

// Bitonic sort of 32 values across lanes, ascending; QW interleaved for ILP.
__device__ __forceinline__ void bitonic32_val(float e[QW], const int lane) {
    #pragma unroll
    for (int k = 2; k <= 32; k <<= 1) {
        #pragma unroll
        for (int s = k >> 1; s > 0; s >>= 1) {
            const bool keepMin = (((lane & s) == 0) == ((lane & k) == 0));
            #pragma unroll
            for (int q = 0; q < QW; ++q) {
                const float oe = __shfl_xor_sync(0xffffffffu, e[q], s);
                const bool takeOther = ((oe < e[q]) == keepMin);
                e[q] = takeOther ? oe : e[q];
            }
        }
    }
}

// Bitonic sort of 32 (d,j) pairs across lanes, ascending lex (validated R6-R14).
__device__ __forceinline__ void bitonic32_pair(float& d, int& j, const int lane) {
    #pragma unroll
    for (int k = 2; k <= 32; k <<= 1) {
        #pragma unroll
        for (int s = k >> 1; s > 0; s >>= 1) {
            const bool keepMin = (((lane & s) == 0) == ((lane & k) == 0));
            const float od = __shfl_xor_sync(0xffffffffu, d, s);
            const int   oj = __shfl_xor_sync(0xffffffffu, j, s);
            const bool takeOther = (dless(od, oj, d, j) == keepMin);
            d = takeOther ? od : d;
            j = takeOther ? oj : j;
        }
    }
}

// ---------------------------------------------------------------------------
// Kernel 1: threshold-filter kNN (EXACT R12: QW=4, full pass0, packed f32x2).
// grid (NN/QB, BB), block 256. SoA smem for LDS.64 paired loads.
// ---------------------------------------------------------------------------
__global__ __launch_bounds__(256, 3) void knn_kernel(const float* __restrict__ x) {
    extern __shared__ float smem_f[];
    float* sxx = smem_f;            // [NN]
    float* syy = smem_f + NN;
    float* szz = smem_f + 2*NN;
    float* sww = smem_f + 3*NN;
    int* s_list = (int*)(smem_f + 4*NN);   // 8 warps * QW * CAP ints

    const int tid = threadIdx.x;
    const int lane = tid & 31;
    const int w = tid >> 5;
    const int b = blockIdx.y;
    const float* xb = x + (size_t)b * NN * 3;

    for (int j = tid; j < NN; j += blockDim.x) {
        float xx = xb[j*3+0], yy = xb[j*3+1], zz = xb[j*3+2];
        sxx[j] = xx; syy[j] = yy; szz[j] = zz;
        sww[j] = fmaf(zz, zz, fmaf(yy, yy, xx*xx));
    }
    __syncthreads();

    int* list = s_list + w * (QW * CAP);

    const int n0 = blockIdx.x * QB + w * QW;
    float qx[QW], qy[QW], qz[QW];
    ull qx2[QW], qy2[QW], qz2[QW];
    #pragma unroll
    for (int q = 0; q < QW; ++q) {
        qx[q] = sxx[n0+q]; qy[q] = syy[n0+q]; qz[q] = szz[n0+q];
        qx2[q] = pack2(qx[q], qx[q]);
        qy2[q] = pack2(qy[q], qy[q]);
        qz2[q] = pack2(qz[q], qz[q]);
    }
    const ull negtwo2 = pack2(-2.0f, -2.0f);

    // --- Pass 0: per-lane min of e over ALL 4096 (2 candidates/lane/iter) -
    float eL[QW], eH[QW];
    #pragma unroll
    for (int q = 0; q < QW; ++q) { eL[q] = FLT_MAX; eH[q] = FLT_MAX; }
    for (int i = 0; i < 64; ++i) {
        const int j0 = i * 64 + 2 * lane;
        const ull cx2 = *(const ull*)&sxx[j0];
        const ull cy2 = *(const ull*)&syy[j0];
        const ull cz2 = *(const ull*)&szz[j0];
        const ull cw2 = *(const ull*)&sww[j0];
        #pragma unroll
        for (int q = 0; q < QW; ++q) {
            ull dot2 = fma2(qz2[q], cz2, fma2(qy2[q], cy2, mul2(qx2[q], cx2)));
            ull ec2 = fma2(negtwo2, dot2, cw2);
            float e0, e1; unpack2(ec2, e0, e1);
            eL[q] = fminf(eL[q], e0);
            eH[q] = fminf(eH[q], e1);
        }
    }
    float m[QW];
    #pragma unroll
    for (int q = 0; q < QW; ++q) m[q] = fminf(eL[q], eH[q]);

    // --- threshold: 10th smallest lane-min + slack (sound superset filter) -
    bitonic32_val(m, lane);
    float Tq[QW];
    #pragma unroll
    for (int q = 0; q < QW; ++q) {
        const float t = __shfl_sync(0xffffffffu, m[q], 9);
        Tq[q] = t + 1e-3f + 1e-5f * fabsf(t);
    }

    // --- Pass 1: packed filter + compact survivors (increasing j order) ----
    int cnt[QW];
    #pragma unroll
    for (int q = 0; q < QW; ++q) cnt[q] = 0;
    for (int i = 0; i < 64; ++i) {
        const int j0 = i * 64 + 2 * lane;
        const ull cx2 = *(const ull*)&sxx[j0];
        const ull cy2 = *(const ull*)&syy[j0];
        const ull cz2 = *(const ull*)&szz[j0];
        const ull cw2 = *(const ull*)&sww[j0];
        #pragma unroll
        for (int q = 0; q < QW; ++q) {
            ull dot2 = fma2(qz2[q], cz2, fma2(qy2[q], cy2, mul2(qx2[q], cx2)));
            ull ec2 = fma2(negtwo2, dot2, cw2);
            float e0, e1; unpack2(ec2, e0, e1);
            const bool k0 = e0 <= Tq[q];
            const bool k1 = e1 <= Tq[q];
            const unsigned b0 = __ballot_sync(0xffffffffu, k0);
            const unsigned b1 = __ballot_sync(0xffffffffu, k1);
            if (b0 | b1) {
                const unsigned lt = (1u << lane) - 1u;
                int pos = cnt[q] + __popc(b0 & lt);
                if (k0 && pos < CAP) list[q*CAP + pos] = j0;
                cnt[q] += __popc(b0);
                pos = cnt[q] + __popc(b1 & lt);
                if (k1 && pos < CAP) list[q*CAP + pos] = j0 + 1;
                cnt[q] += __popc(b1);
            }
        }
    }

    // --- Pass 2: exact d (reference formula) on survivors + bitonic --------
    #pragma unroll
    for (int q = 0; q < QW; ++q) {
        const float q2 = sww[n0 + q];
        int resj;
        if (cnt[q] <= CAP) {
            const bool v = lane < cnt[q];
            int jj = v ? list[q*CAP + lane] : 0x7fffffff;
            float dd = FLT_MAX;
            if (v) {
                const float cxx = sxx[jj], cyy = syy[jj], czz = szz[jj], cww = sww[jj];
                float dot = fmaf(qz[q], czz, fmaf(qy[q], cyy, qx[q] * cxx));
                // match reference: (x2n + x2m) - 2*dot, no fma contraction
                dd = __fsub_rn(__fadd_rn(q2, cww), __fmul_rn(2.0f, dot));
            }
            bitonic32_pair(dd, jj, lane);
            resj = jj;
        } else {
            // fallback (probability ~0 with full pass0): exact R4 ballot scan
            float sd = FLT_MAX; int si = 0x7fffffff;
            float thr_d = FLT_MAX; int thr_j = 0x7fffffff;
            for (int j0 = 0; j0 < NN; j0 += 32) {
                const int j = j0 + lane;
                const float cxx = sxx[j], cyy = syy[j], czz = szz[j], cww = sww[j];
                float dot = fmaf(qz[q], czz, fmaf(qy[q], cyy, qx[q] * cxx));
                float d = __fsub_rn(__fadd_rn(q2, cww), __fmul_rn(2.0f, dot));
                unsigned mask = __ballot_sync(0xffffffffu, dless(d, j, thr_d, thr_j));
                while (mask) {
                    const int src = __ffs(mask) - 1;
                    mask &= mask - 1;
                    const float nd = __shfl_sync(0xffffffffu, d, src);
                    const int   nj = j0 + src;
                    warp_insert(nd, nj, sd, si, lane);
                    thr_d = __shfl_sync(0xffffffffu, sd, 9);
                    thr_j = __shfl_sync(0xffffffffu, si, 9);
                }
            }
            resj = si;
        }
        // slots 1..9 = neighbors (slot 0 = self/nearest, dropped by reference)
        if (lane >= 1 && lane < 10) {
            g_nbr[((size_t)(b * NN) + n0 + q) * KK + (lane - 1)] = resj;
        }
    }
}

// ---------------------------------------------------------------------------
// Kernel 2: gather+phi-sort rel (stored to g_rel) + linear1 -> BN1 partials.
// <<<NBF,128>>>, thread per point. (EXACT R12 structure.)
// ---------------------------------------------------------------------------
__global__ __launch_bounds__(128) void feat_kernel(const float* __restrict__ x,
                                                   const float* __restrict__ W1,
                                                   const float* __restrict__ b1) {
    __shared__ float sW[100], sb[10];
    __shared__ float sred[4*20];
    const int tid = threadIdx.x;
    if (tid < 100) sW[tid] = W1[tid];
    if (tid < 10)  sb[tid] = b1[tid];
    __syncthreads();

    const int gid = blockIdx.x * blockDim.x + tid;
    const int bb = gid >> 12;
    const int n = gid & (NN - 1);
    const float* xb = x + (size_t)bb * NN * 3;
    const float qx = xb[n*3+0], qy = xb[n*3+1], qz = xb[n*3+2];

    float rx[9], ry[9], rz[9], ph[9];
    #pragma unroll
    for (int e = 0; e < 9; ++e) {
        const int idx = g_nbr[(size_t)gid * KK + e];
        rx[e] = xb[idx*3+0] - qx;
        ry[e] = xb[idx*3+1] - qy;
        rz[e] = xb[idx*3+2] - qz;
        ph[e] = atan2f(ry[e], rx[e]);
    }
    // stable ascending bubble sort on phi (matches stable jnp.argsort)
    #pragma unroll
    for (int p = 0; p < 8; ++p) {
        #pragma unroll
        for (int u = 0; u < 8; ++u) {
            if (ph[u+1] < ph[u]) {
                float t;
                t = ph[u]; ph[u] = ph[u+1]; ph[u+1] = t;
                t = rx[u]; rx[u] = rx[u+1]; rx[u+1] = t;
                t = ry[u]; ry[u] = ry[u+1]; ry[u+1] = t;
                t = rz[u]; rz[u] = rz[u+1]; rz[u+1] = t;
            }
        }
    }
    // store sorted rel (SoA, coalesced) for mlp_kernel
    #pragma unroll
    for (int e = 0; e < 9; ++e) {
        g_rel[(3*e+0)*NPTS + gid] = rx[e];
        g_rel[(3*e+1)*NPTS + gid] = ry[e];
        g_rel[(3*e+2)*NPTS + gid] = rz[e];
    }

    float ls[10], ls2[10];
    #pragma unroll
    for (int o = 0; o < 10; ++o) { ls[o] = 0.0f; ls2[o] = 0.0f; }
    float sgn = 1.0f;
    #pragma unroll
    for (int e = 0; e < 9; ++e) {
        const int e2 = (e + 1 == 9) ? 0 : e + 1;
        float ax = rx[e],  ay = ry[e],  az = rz[e];
        float bx = rx[e2], by = ry[e2], bz = rz[e2];
        float cx = 0.5f * (ax + bx), cy = 0.5f * (ay + by), cz = 0.5f * (az + bz);
        float nx = ay*bz - az*by;
        float ny = az*bx - ax*bz;
        float nz = ax*by - ay*bx;
        float nnv = sqrtf(nx*nx + ny*ny + nz*nz);
        float ri = 1.0f / (nnv + 1e-6f);
        nx *= ri; ny *= ri; nz *= ri;
        if (e == 0) sgn = (nx > 0.0f) ? 1.0f : -1.0f;
        nx *= sgn; ny *= sgn; nz *= sgn;
        float pos = (nx*cx + ny*cy + nz*cz) / sqrtf(3.0f);
        float dv = ax*bx + ay*by + az*bz;
        float nA = sqrtf(ax*ax + ay*ay + az*az);
        float nB = sqrtf(bx*bx + by*by + bz*bz);
        float cv = dv / (nA * nB + 1e-8f);
        cv = fminf(1.0f, fmaxf(-1.0f, cv));
        float ang = acosf(cv);
        float f[10] = {cx, cy, cz, nx, ny, nz, pos, ang, nA, nB};
        #pragma unroll
        for (int o = 0; o < 10; ++o) {
            float h = sb[o];
            #pragma unroll
            for (int i = 0; i < 10; ++i) h = fmaf(f[i], sW[o*10+i], h);
            ls[o] += h;
            ls2[o] = fmaf(h, h, ls2[o]);
        }
    }

    const int lane = tid & 31, wid = tid >> 5;
    #pragma unroll
    for (int t = 0; t < 20; ++t) {
        float v = (t < 10) ? ls[t] : ls2[t-10];
        #pragma unroll
        for (int off = 16; off > 0; off >>= 1) v += __shfl_down_sync(0xffffffffu, v, off);
        if (lane == 0) sred[wid*20 + t] = v;
    }
    __syncthreads();
    if (tid < 20) {
        float s = 0.0f;
        #pragma unroll
        for (int ww = 0; ww < 4; ++ww) s += sred[ww*20 + tid];
        g_p1[blockIdx.x * 20 + tid] = s;
    }
}

// ---------------------------------------------------------------------------
// Stats kernel: <<<1,640>>>, warp-per-column. part[nb*20] -> mu, inv.
// ---------------------------------------------------------------------------
__global__ void stats_kernel(int which, int nb) {
    const float* part = which ? g_p2 : g_p1;
    float* outv = which ? g_s2v : g_s1v;
    __shared__ double sums[20];
    const int w = threadIdx.x >> 5, lane = threadIdx.x & 31;
    if (w < 20) {
        double s = 0.0;
        for (int i = lane; i < nb; i += 32) s += (double)part[i*20 + w];
        #pragma unroll
        for (int off = 16; off > 0; off >>= 1)
            s += __shfl_down_sync(0xffffffffu, s, off);
        if (lane == 0) sums[w] = s;
    }
    __syncthreads();
    if (threadIdx.x < 10) {
        const int t = threadIdx.x;
        const float mu = (float)(sums[t] / (double)ROWS);
        const float m2 = (float)(sums[t+10] / (double)ROWS);
        const float var = fmaxf(m2 - mu*mu, 0.0f);
        outv[t] = mu;
        outv[10+t] = rsqrtf(var + 1e-5f);
    }
}

// ---------------------------------------------------------------------------
// Kernel 3: BN1+ReLU+linear2, SPLIT 3-ways over edges, LOW-REG rolled loop.
// grid (NBF, NSPL), block 128, __launch_bounds__(128,6) caps regs at ~85.
// Rows loaded from g_rel inside the (rolled) loop; sgn precomputed with the
// exact R14-validated op sequence. Per-split hmax/hmin + BN2 partials.
// ---------------------------------------------------------------------------
__global__ __launch_bounds__(128, 6) void mlp_kernel(const float* __restrict__ g1v,
                                                     const float* __restrict__ be1,
                                                     const float* __restrict__ W1,
                                                     const float* __restrict__ b1,
                                                     const float* __restrict__ W2,
                                                     const float* __restrict__ b2) {
    __shared__ float sstat[20];
    __shared__ float sW1[100], sb1[10], sW2[100], sb2[10], sg1[10], sbe1[10];
    __shared__ float sred[4*20];
    const int tid = threadIdx.x;
    if (tid < 100) { sW1[tid] = W1[tid]; sW2[tid] = W2[tid]; }
    if (tid < 20) sstat[tid] = g_s1v[tid];
    if (tid < 10) { sb1[tid] = b1[tid]; sb2[tid] = b2[tid];
                    sg1[tid] = g1v[tid]; sbe1[tid] = be1[tid]; }
    __syncthreads();

    const int s = blockIdx.y;                 // 0..2
    const int e0 = s * 3;
    const int gid = blockIdx.x * blockDim.x + tid;

    // sgn from sorted rows 0,1 (identical op order to feat_row e==0; R14-validated)
    float sgn;
    {
        const float ax = g_rel[0*NPTS + gid], ay = g_rel[1*NPTS + gid], az = g_rel[2*NPTS + gid];
        const float bx = g_rel[3*NPTS + gid], by = g_rel[4*NPTS + gid], bz = g_rel[5*NPTS + gid];
        float nx = ay*bz - az*by;
        float ny = az*bx - ax*bz;
        float nz = ax*by - ay*bx;
        float nnv = sqrtf(nx*nx + ny*ny + nz*nz);
        float ri = 1.0f / (nnv + 1e-6f);
        nx *= ri; (void)ny; (void)nz;
        sgn = (nx > 0.0f) ? 1.0f : -1.0f;
    }

    float ls[10], ls2[10], hmax[10], hmin[10];
    #pragma unroll
    for (int o = 0; o < 10; ++o) {
        ls[o] = 0.0f; ls2[o] = 0.0f; hmax[o] = -FLT_MAX; hmin[o] = FLT_MAX;
    }

    #pragma unroll 1
    for (int u = 0; u < 3; ++u) {
        const int e = e0 + u;
        const int e2 = (e + 1 == 9) ? 0 : e + 1;
        const float ax = g_rel[(3*e +0)*NPTS + gid];
        const float ay = g_rel[(3*e +1)*NPTS + gid];
        const float az = g_rel[(3*e +2)*NPTS + gid];
        const float bx = g_rel[(3*e2+0)*NPTS + gid];
        const float by = g_rel[(3*e2+1)*NPTS + gid];
        const float bz = g_rel[(3*e2+2)*NPTS + gid];

        // geometry (exact validated op order, sgn pre-applied)
        float cx = 0.5f * (ax + bx), cy = 0.5f * (ay + by), cz = 0.5f * (az + bz);
        float nx = ay*bz - az*by;
        float ny = az*bx - ax*bz;
        float nz = ax*by - ay*bx;
        float nnv = sqrtf(nx*nx + ny*ny + nz*nz);
        float ri = 1.0f / (nnv + 1e-6f);
        nx *= ri; ny *= ri; nz *= ri;
        nx *= sgn; ny *= sgn; nz *= sgn;
        float pos = (nx*cx + ny*cy + nz*cz) / sqrtf(3.0f);
        float dv = ax*bx + ay*by + az*bz;
        float nA = sqrtf(ax*ax + ay*ay + az*az);
        float nB = sqrtf(bx*bx + by*by + bz*bz);
        float cv = dv / (nA * nB + 1e-8f);
        cv = fminf(1.0f, fmaxf(-1.0f, cv));
        float ang = acosf(cv);
        float f[10] = {cx, cy, cz, nx, ny, nz, pos, ang, nA, nB};

        float a[10];
        #pragma unroll
        for (int o = 0; o < 10; ++o) {
            float h = sb1[o];
            #pragma unroll
            for (int i = 0; i < 10; ++i) h = fmaf(f[i], sW1[o*10+i], h);
            h = ((h - sstat[o]) * sstat[10+o]) * sg1[o] + sbe1[o];
            a[o] = fmaxf(h, 0.0f);
        }
        #pragma unroll
        for (int o = 0; o < 10; ++o) {
            float h = sb2[o];
            #pragma unroll
            for (int i = 0; i < 10; ++i) h = fmaf(a[i], sW2[o*10+i], h);
            ls[o] += h;
            ls2[o] = fmaf(h, h, ls2[o]);
            hmax[o] = fmaxf(hmax[o], h);
            hmin[o] = fminf(hmin[o], h);
        }
    }
    #pragma unroll
    for (int o = 0; o < 10; ++o) {
        g_hmax3[((size_t)s*NPTS + gid)*10 + o] = hmax[o];
        g_hmin3[((size_t)s*NPTS + gid)*10 + o] = hmin[o];
    }

    const int lane = tid & 31, wid = tid >> 5;
    #pragma unroll
    for (int t = 0; t < 20; ++t) {
        float v = (t < 10) ? ls[t] : ls2[t-10];
        #pragma unroll
        for (int off = 16; off > 0; off >>= 1) v += __shfl_down_sync(0xffffffffu, v, off);
        if (lane == 0) sred[wid*20 + t] = v;
    }
    __syncthreads();
    if (tid < 20) {
        float sum = 0.0f;
        #pragma unroll
        for (int ww = 0; ww < 4; ++ww) sum += sred[ww*20 + tid];
        g_p2[(blockIdx.y * gridDim.x + blockIdx.x) * 20 + tid] = sum;
    }
}

// ---------------------------------------------------------------------------
// Kernel 4: combine 3 split partials + monotone max trick + BN2 + ReLU.
// <<<NPTS/128,128>>>. max/min exact-associative => bit-identical to unsplit.
// ---------------------------------------------------------------------------
__global__ __launch_bounds__(128) void out_kernel(const float* __restrict__ g2v,
                                                  const float* __restrict__ be2,
                                                  float* __restrict__ out) {
    __shared__ float sstat[20];
    __shared__ float sg[10], sbe[10];
    const int tid = threadIdx.x;
    if (tid < 20) sstat[tid] = g_s2v[tid];
    if (tid < 10) { sg[tid] = g2v[tid]; sbe[tid] = be2[tid]; }
    __syncthreads();

    const int gid = blockIdx.x * blockDim.x + tid;
    #pragma unroll
    for (int o = 0; o < 10; ++o) {
        const float g = sg[o];
        float h;
        if (g >= 0.0f) {
            h = g_hmax3[(size_t)gid*10 + o];
            h = fmaxf(h, g_hmax3[((size_t)NPTS + gid)*10 + o]);
            h = fmaxf(h, g_hmax3[((size_t)2*NPTS + gid)*10 + o]);
        } else {
            h = g_hmin3[(size_t)gid*10 + o];
            h = fminf(h, g_hmin3[((size_t)NPTS + gid)*10 + o]);
            h = fminf(h, g_hmin3[((size_t)2*NPTS + gid)*10 + o]);
        }
        const float y = fmaxf(((h - sstat[o]) * sstat[10+o]) * g + sbe[o], 0.0f);
        out[(size_t)gid*10 + o] = y;
    }
}

// ---------------------------------------------------------------------------
extern "C" void kernel_launch(void* const* d_in, const int* in_sizes, int n_in,
                              void* d_out, int out_size) {
    (void)in_sizes; (void)n_in; (void)out_size;
    const float* x   = (const float*)d_in[0];
    const float* W1  = (const float*)d_in[1];
    const float* b1  = (const float*)d_in[2];
    const float* g1  = (const float*)d_in[3];
    const float* be1 = (const float*)d_in[4];
    const float* W2  = (const float*)d_in[5];
    const float* b2  = (const float*)d_in[6];
    const float* g2  = (const float*)d_in[7];
    const float* be2 = (const float*)d_in[8];
    float* out = (float*)d_out;

    const int smem1 = 4 * NN * 4 + 8 * QW * CAP * 4;
    cudaFuncSetAttribute(knn_kernel, cudaFuncAttributeMaxDynamicSharedMemorySize, smem1);

    dim3 grid1(NN / QB, BB);
    knn_kernel<<<grid1, 256, smem1>>>(x);
    feat_kernel<<<NBF, 128>>>(x, W1, b1);
    stats_kernel<<<1, 640>>>(0, NBF);
    dim3 grid3(NBF, NSPL);
    mlp_kernel<<<grid3, 128>>>(g1, be1, W1, b1, W2, b2);
    stats_kernel<<<1, 640>>>(1, NBM);
    out_kernel<<<NPTS/128, 128>>>(g2, be2, out);
}

// round 16
// speedup vs baseline: 1.2799x; 1.2799x over previous
#include <cuda_runtime.h>
#include <math.h>
#include <float.h>

#define BB 8
#define NN 4096
#define KK 9
#define NPTS (BB*NN)        /* 32768 */
#define ROWS (NPTS*KK)      /* 294912 */
#define QB 32               /* queries per block (knn) */
#define QW 4                /* queries per warp */
#define CAP 64              /* survivor capacity per query */
#define SAMPLE_ITERS 32     /* pass0 samples first 2048 candidates */
#define NBF 256             /* feat/mlp partial blocks */

typedef unsigned long long ull;

// Scratch (allocation-free: __device__ globals)
__device__ int   g_nbr[NPTS*KK];
__device__ float g_rel[27*NPTS];     // SoA: [(e*3+c)*NPTS + gid]
__device__ float g_p1[NBF*20];
__device__ float g_p2[NBF*20];
__device__ float g_s1v[20];          // mu[10], inv[10]
__device__ float g_s2v[20];
__device__ float g_hmax[NPTS*10];
__device__ float g_hmin[NPTS*10];

__device__ __forceinline__ bool dless(float d1, int j1, float d2, int j2) {
    return d1 < d2 || (d1 == d2 && j1 < j2);
}

// ---- packed f32x2 helpers: two bit-identical fp32 ops per issue -----------
__device__ __forceinline__ ull pack2(float lo, float hi) {
    ull r; asm("mov.b64 %0, {%1, %2};" : "=l"(r) : "f"(lo), "f"(hi)); return r;
}
__device__ __forceinline__ void unpack2(ull v, float& lo, float& hi) {
    asm("mov.b64 {%0, %1}, %2;" : "=f"(lo), "=f"(hi) : "l"(v));
}
__device__ __forceinline__ ull fma2(ull a, ull b, ull c) {
    ull d; asm("fma.rn.f32x2 %0, %1, %2, %3;" : "=l"(d) : "l"(a), "l"(b), "l"(c));
    return d;
}
__device__ __forceinline__ ull mul2(ull a, ull b) {
    ull d; asm("mul.rn.f32x2 %0, %1, %2;" : "=l"(d) : "l"(a), "l"(b)); return d;
}

// Warp-distributed sorted insert into an ascending 32-slot list (lane t =
// slot t). Validated R4-R12.
__device__ __forceinline__ void warp_insert(float nd, int nj, float& sd, int& si,
                                            const int lane) {
    const float pd = __shfl_up_sync(0xffffffffu, sd, 1);
    const int   pi = __shfl_up_sync(0xffffffffu, si, 1);
    const bool pcur  = dless(nd, nj, sd, si);
    const bool pprev = (lane > 0) && dless(nd, nj, pd, pi);
    if (pcur) { sd = pprev ? pd : nd; si = pprev ? pi : nj; }
}

// Bitonic sort of 32 values across lanes, ascending; QW interleaved for ILP.
__device__ __forceinline__ void bitonic32_val(float e[QW], const int lane) {
    #pragma unroll
    for (int k = 2; k <= 32; k <<= 1) {
        #pragma unroll
        for (int s = k >> 1; s > 0; s >>= 1) {
            const bool keepMin = (((lane & s) == 0) == ((lane & k) == 0));
            #pragma unroll
            for (int q = 0; q < QW; ++q) {
                const float oe = __shfl_xor_sync(0xffffffffu, e[q], s);
                const bool takeOther = ((oe < e[q]) == keepMin);
                e[q] = takeOther ? oe : e[q];
            }
        }
    }
}

// Bitonic sort of 32 (d,j) pairs across lanes, ascending lex (validated R6-R12).
__device__ __forceinline__ void bitonic32_pair(float& d, int& j, const int lane) {
    #pragma unroll
    for (int k = 2; k <= 32; k <<= 1) {
        #pragma unroll
        for (int s = k >> 1; s > 0; s >>= 1) {
            const bool keepMin = (((lane & s) == 0) == ((lane & k) == 0));
            const float od = __shfl_xor_sync(0xffffffffu, d, s);
            const int   oj = __shfl_xor_sync(0xffffffffu, j, s);
            const bool takeOther = (dless(od, oj, d, j) == keepMin);
            d = takeOther ? od : d;
            j = takeOther ? oj : j;
        }
    }
}

// ---------------------------------------------------------------------------
// Kernel 1: threshold-filter kNN (R12 structure; pass0 SAMPLED over first
// 2048 candidates, CAP=64 + hybrid exact pass2 so elevated survivor counts
// never trigger the full-scan fallback that sank R9).
// grid (NN/QB, BB), block 256. SoA smem for LDS.64 paired loads.
// ---------------------------------------------------------------------------
__global__ __launch_bounds__(256, 3) void knn_kernel(const float* __restrict__ x) {
    extern __shared__ float smem_f[];
    float* sxx = smem_f;            // [NN]
    float* syy = smem_f + NN;
    float* szz = smem_f + 2*NN;
    float* sww = smem_f + 3*NN;
    int* s_list = (int*)(smem_f + 4*NN);   // 8 warps * QW * CAP ints

    const int tid = threadIdx.x;
    const int lane = tid & 31;
    const int w = tid >> 5;
    const int b = blockIdx.y;
    const float* xb = x + (size_t)b * NN * 3;

    for (int j = tid; j < NN; j += blockDim.x) {
        float xx = xb[j*3+0], yy = xb[j*3+1], zz = xb[j*3+2];
        sxx[j] = xx; syy[j] = yy; szz[j] = zz;
        sww[j] = fmaf(zz, zz, fmaf(yy, yy, xx*xx));
    }
    __syncthreads();

    int* list = s_list + w * (QW * CAP);

    const int n0 = blockIdx.x * QB + w * QW;
    float qx[QW], qy[QW], qz[QW];
    ull qx2[QW], qy2[QW], qz2[QW];
    #pragma unroll
    for (int q = 0; q < QW; ++q) {
        qx[q] = sxx[n0+q]; qy[q] = syy[n0+q]; qz[q] = szz[n0+q];
        qx2[q] = pack2(qx[q], qx[q]);
        qy2[q] = pack2(qy[q], qy[q]);
        qz2[q] = pack2(qz[q], qz[q]);
    }
    const ull negtwo2 = pack2(-2.0f, -2.0f);

    // --- Pass 0 (SAMPLED): per-lane min of e over first 2048 candidates ---
    // e = c.w - 2*dot (q2 constant cancels in comparisons). T from a sample
    // is still >= true 10th (the 10 smallest lane-mins are real candidates),
    // so the filter remains a sound superset; sampling only raises T.
    float eL[QW], eH[QW];
    #pragma unroll
    for (int q = 0; q < QW; ++q) { eL[q] = FLT_MAX; eH[q] = FLT_MAX; }
    for (int i = 0; i < SAMPLE_ITERS; ++i) {
        const int j0 = i * 64 + 2 * lane;
        const ull cx2 = *(const ull*)&sxx[j0];
        const ull cy2 = *(const ull*)&syy[j0];
        const ull cz2 = *(const ull*)&szz[j0];
        const ull cw2 = *(const ull*)&sww[j0];
        #pragma unroll
        for (int q = 0; q < QW; ++q) {
            ull dot2 = fma2(qz2[q], cz2, fma2(qy2[q], cy2, mul2(qx2[q], cx2)));
            ull ec2 = fma2(negtwo2, dot2, cw2);
            float e0, e1; unpack2(ec2, e0, e1);
            eL[q] = fminf(eL[q], e0);
            eH[q] = fminf(eH[q], e1);
        }
    }
    float m[QW];
    #pragma unroll
    for (int q = 0; q < QW; ++q) m[q] = fminf(eL[q], eH[q]);

    // --- threshold: 10th smallest lane-min + slack (sound superset filter) -
    bitonic32_val(m, lane);
    float Tq[QW];
    #pragma unroll
    for (int q = 0; q < QW; ++q) {
        const float t = __shfl_sync(0xffffffffu, m[q], 9);
        Tq[q] = t + 1e-3f + 1e-5f * fabsf(t);
    }

    // --- Pass 1: packed filter over ALL 4096 + compact survivors ----------
    int cnt[QW];
    #pragma unroll
    for (int q = 0; q < QW; ++q) cnt[q] = 0;
    for (int i = 0; i < 64; ++i) {
        const int j0 = i * 64 + 2 * lane;
        const ull cx2 = *(const ull*)&sxx[j0];
        const ull cy2 = *(const ull*)&syy[j0];
        const ull cz2 = *(const ull*)&szz[j0];
        const ull cw2 = *(const ull*)&sww[j0];
        #pragma unroll
        for (int q = 0; q < QW; ++q) {
            ull dot2 = fma2(qz2[q], cz2, fma2(qy2[q], cy2, mul2(qx2[q], cx2)));
            ull ec2 = fma2(negtwo2, dot2, cw2);
            float e0, e1; unpack2(ec2, e0, e1);
            const bool k0 = e0 <= Tq[q];
            const bool k1 = e1 <= Tq[q];
            const unsigned b0 = __ballot_sync(0xffffffffu, k0);
            const unsigned b1 = __ballot_sync(0xffffffffu, k1);
            if (b0 | b1) {
                const unsigned lt = (1u << lane) - 1u;
                int pos = cnt[q] + __popc(b0 & lt);
                if (k0 && pos < CAP) list[q*CAP + pos] = j0;
                cnt[q] += __popc(b0);
                pos = cnt[q] + __popc(b1 & lt);
                if (k1 && pos < CAP) list[q*CAP + pos] = j0 + 1;
                cnt[q] += __popc(b1);
            }
        }
    }

    // --- Pass 2: exact d (reference formula) on survivors -----------------
    #pragma unroll
    for (int q = 0; q < QW; ++q) {
        const float q2 = sww[n0 + q];
        int resj;
        if (cnt[q] <= 32) {
            // common path (~97%): one bitonic sort
            const bool v = lane < cnt[q];
            int jj = v ? list[q*CAP + lane] : 0x7fffffff;
            float dd = FLT_MAX;
            if (v) {
                const float cxx = sxx[jj], cyy = syy[jj], czz = szz[jj], cww = sww[jj];
                float dot = fmaf(qz[q], czz, fmaf(qy[q], cyy, qx[q] * cxx));
                // match reference: (x2n + x2m) - 2*dot, no fma contraction
                dd = __fsub_rn(__fadd_rn(q2, cww), __fmul_rn(2.0f, dot));
            }
            bitonic32_pair(dd, jj, lane);
            resj = jj;
        } else if (cnt[q] <= CAP) {
            // middle path (~3%): sort first 32, sorted-insert the rest
            int jj = list[q*CAP + lane];
            float dd;
            {
                const float cxx = sxx[jj], cyy = syy[jj], czz = szz[jj], cww = sww[jj];
                float dot = fmaf(qz[q], czz, fmaf(qy[q], cyy, qx[q] * cxx));
                dd = __fsub_rn(__fadd_rn(q2, cww), __fmul_rn(2.0f, dot));
            }
            bitonic32_pair(dd, jj, lane);
            for (int s = 32; s < cnt[q]; ++s) {
                const int nj = list[q*CAP + s];        // LDS broadcast
                const float cxx = sxx[nj], cyy = syy[nj], czz = szz[nj], cww = sww[nj];
                float dot = fmaf(qz[q], czz, fmaf(qy[q], cyy, qx[q] * cxx));
                const float nd = __fsub_rn(__fadd_rn(q2, cww), __fmul_rn(2.0f, dot));
                warp_insert(nd, nj, dd, jj, lane);
            }
            resj = jj;
        } else {
            // fallback (P ~ 0 at CAP=64): exact R4 ballot scan
            float sd = FLT_MAX; int si = 0x7fffffff;
            float thr_d = FLT_MAX; int thr_j = 0x7fffffff;
            for (int j0 = 0; j0 < NN; j0 += 32) {
                const int j = j0 + lane;
                const float cxx = sxx[j], cyy = syy[j], czz = szz[j], cww = sww[j];
                float dot = fmaf(qz[q], czz, fmaf(qy[q], cyy, qx[q] * cxx));
                float d = __fsub_rn(__fadd_rn(q2, cww), __fmul_rn(2.0f, dot));
                unsigned mask = __ballot_sync(0xffffffffu, dless(d, j, thr_d, thr_j));
                while (mask) {
                    const int src = __ffs(mask) - 1;
                    mask &= mask - 1;
                    const float nd = __shfl_sync(0xffffffffu, d, src);
                    const int   nj = j0 + src;
                    warp_insert(nd, nj, sd, si, lane);
                    thr_d = __shfl_sync(0xffffffffu, sd, 9);
                    thr_j = __shfl_sync(0xffffffffu, si, 9);
                }
            }
            resj = si;
        }
        // slots 1..9 = neighbors (slot 0 = self/nearest, dropped by reference)
        if (lane >= 1 && lane < 10) {
            g_nbr[((size_t)(b * NN) + n0 + q) * KK + (lane - 1)] = resj;
        }
    }
}

// Compute feature row e from sorted rel (identical fp-ops everywhere).
__device__ __forceinline__ void feat_row(const float rx[9], const float ry[9],
                                         const float rz[9], int e, float& sgn,
                                         float f[10]) {
    const int e2 = (e + 1 == 9) ? 0 : e + 1;
    float ax = rx[e],  ay = ry[e],  az = rz[e];
    float bx = rx[e2], by = ry[e2], bz = rz[e2];
    float cx = 0.5f * (ax + bx), cy = 0.5f * (ay + by), cz = 0.5f * (az + bz);
    float nx = ay*bz - az*by;
    float ny = az*bx - ax*bz;
    float nz = ax*by - ay*bx;
    float nnv = sqrtf(nx*nx + ny*ny + nz*nz);
    float ri = 1.0f / (nnv + 1e-6f);
    nx *= ri; ny *= ri; nz *= ri;
    if (e == 0) sgn = (nx > 0.0f) ? 1.0f : -1.0f;
    nx *= sgn; ny *= sgn; nz *= sgn;
    float pos = (nx*cx + ny*cy + nz*cz) / sqrtf(3.0f);
    float dv = ax*bx + ay*by + az*bz;
    float nA = sqrtf(ax*ax + ay*ay + az*az);
    float nB = sqrtf(bx*bx + by*by + bz*bz);
    float cv = dv / (nA * nB + 1e-8f);
    cv = fminf(1.0f, fmaxf(-1.0f, cv));
    float ang = acosf(cv);
    f[0]=cx; f[1]=cy; f[2]=cz; f[3]=nx; f[4]=ny; f[5]=nz;
    f[6]=pos; f[7]=ang; f[8]=nA; f[9]=nB;
}

// ---------------------------------------------------------------------------
// Kernel 2: gather+phi-sort rel (stored to g_rel) + linear1 -> BN1 partials.
// <<<NBF,128>>>, thread per point. (EXACT R12 structure.)
// ---------------------------------------------------------------------------
__global__ __launch_bounds__(128) void feat_kernel(const float* __restrict__ x,
                                                   const float* __restrict__ W1,
                                                   const float* __restrict__ b1) {
    __shared__ float sW[100], sb[10];
    __shared__ float sred[4*20];
    const int tid = threadIdx.x;
    if (tid < 100) sW[tid] = W1[tid];
    if (tid < 10)  sb[tid] = b1[tid];
    __syncthreads();

    const int gid = blockIdx.x * blockDim.x + tid;
    const int bb = gid >> 12;
    const int n = gid & (NN - 1);
    const float* xb = x + (size_t)bb * NN * 3;
    const float qx = xb[n*3+0], qy = xb[n*3+1], qz = xb[n*3+2];

    float rx[9], ry[9], rz[9], ph[9];
    #pragma unroll
    for (int e = 0; e < 9; ++e) {
        const int idx = g_nbr[(size_t)gid * KK + e];
        rx[e] = xb[idx*3+0] - qx;
        ry[e] = xb[idx*3+1] - qy;
        rz[e] = xb[idx*3+2] - qz;
        ph[e] = atan2f(ry[e], rx[e]);
    }
    // stable ascending bubble sort on phi (matches stable jnp.argsort)
    #pragma unroll
    for (int p = 0; p < 8; ++p) {
        #pragma unroll
        for (int u = 0; u < 8; ++u) {
            if (ph[u+1] < ph[u]) {
                float t;
                t = ph[u]; ph[u] = ph[u+1]; ph[u+1] = t;
                t = rx[u]; rx[u] = rx[u+1]; rx[u+1] = t;
                t = ry[u]; ry[u] = ry[u+1]; ry[u+1] = t;
                t = rz[u]; rz[u] = rz[u+1]; rz[u+1] = t;
            }
        }
    }
    // store sorted rel (SoA, coalesced) for mlp_kernel
    #pragma unroll
    for (int e = 0; e < 9; ++e) {
        g_rel[(3*e+0)*NPTS + gid] = rx[e];
        g_rel[(3*e+1)*NPTS + gid] = ry[e];
        g_rel[(3*e+2)*NPTS + gid] = rz[e];
    }

    float ls[10], ls2[10];
    #pragma unroll
    for (int o = 0; o < 10; ++o) { ls[o] = 0.0f; ls2[o] = 0.0f; }
    float sgn = 1.0f;
    #pragma unroll
    for (int e = 0; e < 9; ++e) {
        float f[10];
        feat_row(rx, ry, rz, e, sgn, f);
        #pragma unroll
        for (int o = 0; o < 10; ++o) {
            float h = sb[o];
            #pragma unroll
            for (int i = 0; i < 10; ++i) h = fmaf(f[i], sW[o*10+i], h);
            ls[o] += h;
            ls2[o] = fmaf(h, h, ls2[o]);
        }
    }

    const int lane = tid & 31, wid = tid >> 5;
    #pragma unroll
    for (int t = 0; t < 20; ++t) {
        float v = (t < 10) ? ls[t] : ls2[t-10];
        #pragma unroll
        for (int off = 16; off > 0; off >>= 1) v += __shfl_down_sync(0xffffffffu, v, off);
        if (lane == 0) sred[wid*20 + t] = v;
    }
    __syncthreads();
    if (tid < 20) {
        float s = 0.0f;
        #pragma unroll
        for (int ww = 0; ww < 4; ++ww) s += sred[ww*20 + tid];
        g_p1[blockIdx.x * 20 + tid] = s;
    }
}

// ---------------------------------------------------------------------------
// Stats kernel: <<<1,640>>>, warp-per-column. part[256*20] -> mu, inv.
// Deterministic fixed-order reduction. (EXACT R12.)
// ---------------------------------------------------------------------------
__global__ void stats_kernel(int which) {
    const float* part = which ? g_p2 : g_p1;
    float* outv = which ? g_s2v : g_s1v;
    __shared__ double sums[20];
    const int w = threadIdx.x >> 5, lane = threadIdx.x & 31;
    if (w < 20) {
        double s = 0.0;
        for (int i = lane; i < NBF; i += 32) s += (double)part[i*20 + w];
        #pragma unroll
        for (int off = 16; off > 0; off >>= 1)
            s += __shfl_down_sync(0xffffffffu, s, off);
        if (lane == 0) sums[w] = s;
    }
    __syncthreads();
    if (threadIdx.x < 10) {
        const int t = threadIdx.x;
        const float mu = (float)(sums[t] / (double)ROWS);
        const float m2 = (float)(sums[t+10] / (double)ROWS);
        const float var = fmaxf(m2 - mu*mu, 0.0f);
        outv[t] = mu;
        outv[10+t] = rsqrtf(var + 1e-5f);
    }
}

// ---------------------------------------------------------------------------
// Kernel 3: BN1+ReLU+linear2 from stored rel; per-point hmax/hmin + BN2
// partials. <<<NBF,128>>>, thread per point. (EXACT R12: 255 regs is fine,
// 17.3us accepted; R13-R15 proved restructuring loses.)
// ---------------------------------------------------------------------------
__global__ __launch_bounds__(128) void mlp_kernel(const float* __restrict__ g1v,
                                                  const float* __restrict__ be1,
                                                  const float* __restrict__ W1,
                                                  const float* __restrict__ b1,
                                                  const float* __restrict__ W2,
                                                  const float* __restrict__ b2) {
    __shared__ float sstat[20];
    __shared__ float sW1[100], sb1[10], sW2[100], sb2[10], sg1[10], sbe1[10];
    __shared__ float sred[4*20];
    const int tid = threadIdx.x;
    if (tid < 100) { sW1[tid] = W1[tid]; sW2[tid] = W2[tid]; }
    if (tid < 20) sstat[tid] = g_s1v[tid];
    if (tid < 10) { sb1[tid] = b1[tid]; sb2[tid] = b2[tid];
                    sg1[tid] = g1v[tid]; sbe1[tid] = be1[tid]; }
    __syncthreads();

    const int gid = blockIdx.x * blockDim.x + tid;
    float rx[9], ry[9], rz[9];
    #pragma unroll
    for (int e = 0; e < 9; ++e) {
        rx[e] = g_rel[(3*e+0)*NPTS + gid];
        ry[e] = g_rel[(3*e+1)*NPTS + gid];
        rz[e] = g_rel[(3*e+2)*NPTS + gid];
    }

    float ls[10], ls2[10], hmax[10], hmin[10];
    #pragma unroll
    for (int o = 0; o < 10; ++o) {
        ls[o] = 0.0f; ls2[o] = 0.0f; hmax[o] = -FLT_MAX; hmin[o] = FLT_MAX;
    }
    float sgn = 1.0f;
    #pragma unroll
    for (int e = 0; e < 9; ++e) {
        float f[10];
        feat_row(rx, ry, rz, e, sgn, f);
        float a[10];
        #pragma unroll
        for (int o = 0; o < 10; ++o) {
            float h = sb1[o];
            #pragma unroll
            for (int i = 0; i < 10; ++i) h = fmaf(f[i], sW1[o*10+i], h);
            h = ((h - sstat[o]) * sstat[10+o]) * sg1[o] + sbe1[o];
            a[o] = fmaxf(h, 0.0f);
        }
        #pragma unroll
        for (int o = 0; o < 10; ++o) {
            float h = sb2[o];
            #pragma unroll
            for (int i = 0; i < 10; ++i) h = fmaf(a[i], sW2[o*10+i], h);
            ls[o] += h;
            ls2[o] = fmaf(h, h, ls2[o]);
            hmax[o] = fmaxf(hmax[o], h);
            hmin[o] = fminf(hmin[o], h);
        }
    }
    #pragma unroll
    for (int o = 0; o < 10; ++o) {
        g_hmax[gid*10 + o] = hmax[o];
        g_hmin[gid*10 + o] = hmin[o];
    }

    const int lane = tid & 31, wid = tid >> 5;
    #pragma unroll
    for (int t = 0; t < 20; ++t) {
        float v = (t < 10) ? ls[t] : ls2[t-10];
        #pragma unroll
        for (int off = 16; off > 0; off >>= 1) v += __shfl_down_sync(0xffffffffu, v, off);
        if (lane == 0) sred[wid*20 + t] = v;
    }
    __syncthreads();
    if (tid < 20) {
        float s = 0.0f;
        #pragma unroll
        for (int ww = 0; ww < 4; ++ww) s += sred[ww*20 + tid];
        g_p2[blockIdx.x * 20 + tid] = s;
    }
}

// ---------------------------------------------------------------------------
// Kernel 4: monotone max trick + BN2 + ReLU. <<<NPTS/128,128>>> (EXACT R12.)
// max_k relu(aff(h)) = relu(aff(max_k h)) for g>=0, relu(aff(min_k h)) g<0.
// ---------------------------------------------------------------------------
__global__ __launch_bounds__(128) void out_kernel(const float* __restrict__ g2v,
                                                  const float* __restrict__ be2,
                                                  float* __restrict__ out) {
    __shared__ float sstat[20];
    __shared__ float sg[10], sbe[10];
    const int tid = threadIdx.x;
    if (tid < 20) sstat[tid] = g_s2v[tid];
    if (tid < 10) { sg[tid] = g2v[tid]; sbe[tid] = be2[tid]; }
    __syncthreads();

    const int gid = blockIdx.x * blockDim.x + tid;
    #pragma unroll
    for (int o = 0; o < 10; ++o) {
        const float g = sg[o];
        const float h = (g >= 0.0f) ? g_hmax[gid*10 + o] : g_hmin[gid*10 + o];
        const float y = fmaxf(((h - sstat[o]) * sstat[10+o]) * g + sbe[o], 0.0f);
        out[gid*10 + o] = y;
    }
}

// ---------------------------------------------------------------------------
extern "C" void kernel_launch(void* const* d_in, const int* in_sizes, int n_in,
                              void* d_out, int out_size) {
    (void)in_sizes; (void)n_in; (void)out_size;
    const float* x   = (const float*)d_in[0];
    const float* W1  = (const float*)d_in[1];
    const float* b1  = (const float*)d_in[2];
    const float* g1  = (const float*)d_in[3];
    const float* be1 = (const float*)d_in[4];
    const float* W2  = (const float*)d_in[5];
    const float* b2  = (const float*)d_in[6];
    const float* g2  = (const float*)d_in[7];
    const float* be2 = (const float*)d_in[8];
    float* out = (float*)d_out;

    const int smem1 = 4 * NN * 4 + 8 * QW * CAP * 4;
    cudaFuncSetAttribute(knn_kernel, cudaFuncAttributeMaxDynamicSharedMemorySize, smem1);

    dim3 grid1(NN / QB, BB);
    knn_kernel<<<grid1, 256, smem1>>>(x);
    feat_kernel<<<NBF, 128>>>(x, W1, b1);
    stats_kernel<<<1, 640>>>(0);
    mlp_kernel<<<NBF, 128>>>(g1, be1, W1, b1, W2, b2);
    stats_kernel<<<1, 640>>>(1);
    out_kernel<<<NPTS/128, 128>>>(g2, be2, out);
}